// round 8
// baseline (speedup 1.0000x reference)
#include <cuda_runtime.h>
#include <cstdint>

#define NN 500
#define GG 128
#define HH 200
#define WW 304
#define HWPX (HH * WW)            // 60800
#define WORDS 1900                // HWPX/32 exact
#define WSTRIDE 1920              // padded bit-row stride (u32), 16B multiple
#define MAXPAIRS (NN * (NN - 1) / 2)
#define MASK_THR 0.005f
#define SIGMA 2.0f

#define NCHUNK 16                 // chunks per grid row
#define CHUNKW 120                // words per chunk (last chunk: 100)

// ---- device scratch (zero-init at load; popc final phase resets per replay) ----
__device__ __align__(16) unsigned int g_bits[NN * WSTRIDE];
__device__ float g_areaf[NN];               // exact small-int float sums: order-invariant
__device__ float g_part[NN * NCHUNK];       // per-(mask,chunk) soft sums, single writer
__device__ float g_comp[NN];                // comp_iou (0 at entry)
__device__ int   g_npairs;                  // 0 at entry
__device__ unsigned int g_done;             // last-CTA counter (0 at entry)
__device__ unsigned int g_pair_ij[MAXPAIRS];
__device__ float g_pair_d[MAXPAIRS];

// ============================================================
// Kernel 1: x-row-stationary decode.
// CTA = (x-row, chunk): loads its x chunk to smem ONCE, scans
// x_inds to find all masks with xi == row, then streams each
// mask's y chunk from global (L2-cached). Bits packed in ballot
// order (fixed pixel permutation: invariant for AND/popc/sums).
// ============================================================
__global__ __launch_bounds__(256) void decode_kernel(
    const float* __restrict__ segx,
    const float* __restrict__ segy,
    const int* __restrict__ x_inds,
    const int* __restrict__ y_inds)
{
    __shared__ float sxc[CHUNKW * 32];      // 3840 floats = 15360 B
    __shared__ int   s_list[NN];
    __shared__ int   s_cnt;
    __shared__ float s_sum[8];
    __shared__ float s_area[8];

    const int row  = blockIdx.x >> 4;
    const int c    = blockIdx.x & 15;
    const int tid  = threadIdx.x;
    const int warp = tid >> 5;
    const int lane = tid & 31;

    const int w0     = c * CHUNKW;
    const int nquads = (c == NCHUNK - 1) ? 25 : 30;   // quads of 128 px
    const int npx4   = nquads * 32;                   // float4 count (960/800)

    if (tid == 0) s_cnt = 0;

    // load x chunk into smem (coalesced float4)
    const float4* __restrict__ rx4 =
        reinterpret_cast<const float4*>(segx + (size_t)row * HWPX) + w0 * 8;
    for (int i = tid; i < npx4; i += 256)
        reinterpret_cast<float4*>(sxc)[i] = rx4[i];
    __syncthreads();

    // build the group: masks whose x row is ours
    for (int k = tid; k < NN; k += 256)
        if (x_inds[k] == row) {
            int p = atomicAdd(&s_cnt, 1);
            s_list[p] = k;
        }
    __syncthreads();
    const int cnt = s_cnt;

    for (int g = 0; g < cnt; g++) {
        const int m  = s_list[g];
        const int yi = y_inds[m];
        const float4* __restrict__ ry4 =
            reinterpret_cast<const float4*>(segy + (size_t)yi * HWPX) + w0 * 8;

        float ssum  = 0.0f;
        float areaf = 0.0f;
        uint4* pw = reinterpret_cast<uint4*>(g_bits + m * WSTRIDE + w0) + warp;

        for (int k = warp; k < nquads; k += 8, pw += 8) {
            const float4 a = reinterpret_cast<const float4*>(sxc)[k * 32 + lane];
            const float4 b = ry4[k * 32 + lane];
            const float s0 = a.x * b.x;
            const float s1 = a.y * b.y;
            const float s2 = a.z * b.z;
            const float s3 = a.w * b.w;
            const bool p0 = s0 > MASK_THR;
            const bool p1 = s1 > MASK_THR;
            const bool p2 = s2 > MASK_THR;
            const bool p3 = s3 > MASK_THR;
            const unsigned b0 = __ballot_sync(0xffffffffu, p0);
            const unsigned b1 = __ballot_sync(0xffffffffu, p1);
            const unsigned b2 = __ballot_sync(0xffffffffu, p2);
            const unsigned b3 = __ballot_sync(0xffffffffu, p3);
            if (p0) { ssum += s0; areaf += 1.0f; }
            if (p1) { ssum += s1; areaf += 1.0f; }
            if (p2) { ssum += s2; areaf += 1.0f; }
            if (p3) { ssum += s3; areaf += 1.0f; }
            if (lane == 0)
                *pw = make_uint4(b0, b1, b2, b3);
        }

        // per-mask block reduction
#pragma unroll
        for (int off = 16; off > 0; off >>= 1) {
            ssum  += __shfl_down_sync(0xffffffffu, ssum,  off);
            areaf += __shfl_down_sync(0xffffffffu, areaf, off);
        }
        if (lane == 0) { s_sum[warp] = ssum; s_area[warp] = areaf; }
        __syncthreads();
        if (tid == 0) {
            float tsum = 0.0f, tarea = 0.0f;
#pragma unroll
            for (int k = 0; k < 8; k++) { tsum += s_sum[k]; tarea += s_area[k]; }
            g_part[m * NCHUNK + c] = tsum;       // single writer: deterministic
            atomicAdd(&g_areaf[m], tarea);       // exact int-valued float: order-invariant
        }
        // last chunk zeroes this mask's pad words [1900,1920)
        if (c == NCHUNK - 1 && tid < WSTRIDE - WORDS)
            g_bits[m * WSTRIDE + WORDS + tid] = 0u;
        __syncthreads();                          // protect s_sum reuse
    }
}

// ============================================================
// Kernel 2: fused pair enumeration + popcount intersection,
// with last-CTA final phase (scores + decay + output + reset).
// ============================================================
__global__ __launch_bounds__(256) void popc_kernel(
    const int* __restrict__ labels,
    const float* __restrict__ cate_scores,
    float* __restrict__ out)
{
    __shared__ int s_lab[NN];
    __shared__ unsigned s_last;
    const int tid  = threadIdx.x;
    const int lane = tid & 31;
    const int gwarp = (blockIdx.x * 256 + tid) >> 5;
    const int NW = gridDim.x * 8;

    for (int k = tid; k < NN; k += 256) s_lab[k] = labels[k];
    __syncthreads();

    for (int p = gwarp; p < NN * NN; p += NW) {
        const int i = p / NN;
        const int j = p - i * NN;
        if (j <= i) continue;
        if (s_lab[i] != s_lab[j]) continue;

        const uint4* __restrict__ bi = reinterpret_cast<const uint4*>(g_bits + i * WSTRIDE);
        const uint4* __restrict__ bj = reinterpret_cast<const uint4*>(g_bits + j * WSTRIDE);

        int inter = 0;
#pragma unroll 5
        for (int w = lane; w < WSTRIDE / 4; w += 32) {   // 15 iterations
            uint4 a = bi[w];
            uint4 b = bj[w];
            inter += __popc(a.x & b.x) + __popc(a.y & b.y)
                   + __popc(a.z & b.z) + __popc(a.w & b.w);
        }
#pragma unroll
        for (int off = 16; off > 0; off >>= 1)
            inter += __shfl_down_sync(0xffffffffu, inter, off);

        if (lane == 0) {
            float uni = g_areaf[i] + g_areaf[j] - (float)inter;
            float iou = (float)inter / fmaxf(uni, 1e-6f);
            atomicMax(reinterpret_cast<int*>(&g_comp[j]), __float_as_int(iou)); // iou>=0
            int pos = atomicAdd(&g_npairs, 1);
            g_pair_ij[pos] = ((unsigned)i << 16) | (unsigned)j;
            g_pair_d[pos] = iou;
        }
    }

    // ---- last CTA runs the final phase ----
    __threadfence();
    if (tid == 0)
        s_last = (atomicAdd(&g_done, 1u) == (unsigned)gridDim.x - 1u);
    __syncthreads();
    if (!s_last) return;

    __shared__ float s_coef[NN];
    __shared__ float s_score[NN];

    // phase 1: fixed-order reduce of chunk partials per mask
    for (int n = tid; n < NN; n += 256) {
        float acc = 0.0f;
#pragma unroll
        for (int k = 0; k < NCHUNK; k++) acc += g_part[n * NCHUNK + k];
        s_score[n] = cate_scores[n] * (acc / fmaxf(g_areaf[n], 1.0f));
        s_coef[n] = 1.0f;
    }
    __syncthreads();

    // phase 2: decay terms -> order-independent min into smem coef
    const int np = g_npairs;
    for (int p = tid; p < np; p += 256) {
        const unsigned ij = g_pair_ij[p];
        const int i = (int)(ij >> 16);
        const int j = (int)(ij & 0xffffu);
        const float d = g_pair_d[p];
        const float c = g_comp[i];
        const float term = __expf(SIGMA * (c * c - d * d));   // > 0
        atomicMin(reinterpret_cast<int*>(&s_coef[j]), __float_as_int(term));
    }
    __syncthreads();

    // phase 3: output + reset accumulators for next replay
    for (int n = tid; n < NN; n += 256) {
        out[n] = s_score[n] * fminf(s_coef[n], 1.0f);
        g_areaf[n] = 0.0f;
        g_comp[n] = 0.0f;
    }
    if (tid == 0) { g_npairs = 0; g_done = 0u; }
}

extern "C" void kernel_launch(void* const* d_in, const int* in_sizes, int n_in,
                              void* d_out, int out_size)
{
    const float* cate_scores = (const float*)d_in[0];
    const float* segx        = (const float*)d_in[1];
    const float* segy        = (const float*)d_in[2];
    const int*   labels      = (const int*)d_in[3];
    const int*   x_inds      = (const int*)d_in[4];
    const int*   y_inds      = (const int*)d_in[5];
    float* out = (float*)d_out;

    decode_kernel<<<GG * NCHUNK, 256>>>(segx, segy, x_inds, y_inds);
    popc_kernel<<<304, 256>>>(labels, cate_scores, out);
}

// round 9
// speedup vs baseline: 1.7469x; 1.7469x over previous
#include <cuda_runtime.h>
#include <cstdint>

#define NN 500
#define GG 128
#define HH 200
#define WW 304
#define HWPX (HH * WW)            // 60800
#define WORDS 1900                // HWPX/32 exact
#define WSTRIDE 1920              // padded bit-row stride (u32), 16B multiple
#define MAXPAIRS (NN * (NN - 1) / 2)
#define MASK_THR 0.005f
#define SIGMA 2.0f

#define NCHUNK 8                  // chunks per mask
#define CHUNKW 240                // words per chunk (last: 220). multiple of 4.

#define POPC_BLOCKS 304
#define CELLS_PER_CTA ((NN * NN + POPC_BLOCKS - 1) / POPC_BLOCKS)   // 823
#define LMAX 832                  // local pair list capacity >= CELLS_PER_CTA

// ---- device scratch (zero-init at load; decayfinal resets per replay) ----
__device__ __align__(16) unsigned int g_bits[NN * WSTRIDE];
__device__ float g_areaf[NN];             // exact small-int float sums: order-invariant
__device__ float g_part8[NN * NCHUNK];    // per-(mask,chunk) soft sums, single writer
__device__ float g_comp[NN];              // comp_iou (0 at entry)
__device__ int   g_npairs;                // 0 at entry
__device__ unsigned int g_pair_ij[MAXPAIRS];
__device__ float g_pair_d[MAXPAIRS];

// ============================================================
// Kernel 1: decode (R7 form, proven 24us = LTS-cap bound).
// Warp iteration = 128 consecutive pixels (lane L loads float4 #L).
// Bits packed in ballot order (fixed pixel permutation: invariant
// for AND/popc/area/sums). blockIdx.x = mask*8 + chunk.
// ============================================================
__global__ __launch_bounds__(256) void decode_kernel(
    const float* __restrict__ segx,
    const float* __restrict__ segy,
    const int* __restrict__ x_inds,
    const int* __restrict__ y_inds)
{
    const int n    = blockIdx.x >> 3;
    const int c    = blockIdx.x & 7;
    const int tid  = threadIdx.x;
    const int warp = tid >> 5;
    const int lane = tid & 31;

    const int xi = x_inds[n];
    const int yi = y_inds[n];
    const float4* __restrict__ rx = reinterpret_cast<const float4*>(segx + (size_t)xi * HWPX);
    const float4* __restrict__ ry = reinterpret_cast<const float4*>(segy + (size_t)yi * HWPX);

    const int w0 = c * CHUNKW;
    const int nquads = ((c == NCHUNK - 1) ? (WORDS - w0) : CHUNKW) >> 2;   // 60 or 55

    float ssum  = 0.0f;
    float areaf = 0.0f;

    const float4* pa = rx + (size_t)w0 * 8 + warp * 32 + lane;
    const float4* pb = ry + (size_t)w0 * 8 + warp * 32 + lane;
    uint4* pw = reinterpret_cast<uint4*>(g_bits + n * WSTRIDE + w0) + warp;

    for (int k = warp; k < nquads; k += 8, pa += 256, pb += 256, pw += 8) {
        const float4 a = *pa;
        const float4 b = *pb;
        const float s0 = a.x * b.x;
        const float s1 = a.y * b.y;
        const float s2 = a.z * b.z;
        const float s3 = a.w * b.w;
        const bool p0 = s0 > MASK_THR;
        const bool p1 = s1 > MASK_THR;
        const bool p2 = s2 > MASK_THR;
        const bool p3 = s3 > MASK_THR;
        const unsigned b0 = __ballot_sync(0xffffffffu, p0);
        const unsigned b1 = __ballot_sync(0xffffffffu, p1);
        const unsigned b2 = __ballot_sync(0xffffffffu, p2);
        const unsigned b3 = __ballot_sync(0xffffffffu, p3);
        if (p0) { ssum += s0; areaf += 1.0f; }
        if (p1) { ssum += s1; areaf += 1.0f; }
        if (p2) { ssum += s2; areaf += 1.0f; }
        if (p3) { ssum += s3; areaf += 1.0f; }
        if (lane == 0)
            *pw = make_uint4(b0, b1, b2, b3);
    }
    // last chunk zeroes the pad words [1900,1920)
    if (c == NCHUNK - 1 && tid < WSTRIDE - WORDS)
        g_bits[n * WSTRIDE + WORDS + tid] = 0u;

    // block reduction (8 warps, two floats)
    __shared__ float s_sum[8];
    __shared__ float s_area[8];
#pragma unroll
    for (int off = 16; off > 0; off >>= 1) {
        ssum  += __shfl_down_sync(0xffffffffu, ssum,  off);
        areaf += __shfl_down_sync(0xffffffffu, areaf, off);
    }
    if (lane == 0) { s_sum[warp] = ssum; s_area[warp] = areaf; }
    __syncthreads();
    if (tid == 0) {
        float tsum = 0.0f, tarea = 0.0f;
#pragma unroll
        for (int k = 0; k < 8; k++) { tsum += s_sum[k]; tarea += s_area[k]; }
        g_part8[n * NCHUNK + c] = tsum;      // single writer: deterministic
        atomicAdd(&g_areaf[n], tarea);       // exact int-valued float: order-invariant
    }
}

// ============================================================
// Kernel 2: popc with CTA-local pair building.
// Phase 1: threads gate the CTA's 823-cell slice against smem
// labels, appending matches to a local list (no warp-serialized
// enumeration). Phase 2: warps consume the local list.
// ============================================================
__global__ __launch_bounds__(256) void popc_kernel(const int* __restrict__ labels)
{
    __shared__ int s_lab[NN];
    __shared__ unsigned s_pairs[LMAX];
    __shared__ int s_cnt;
    const int tid  = threadIdx.x;
    const int lane = tid & 31;
    const int warp = tid >> 5;

    if (tid == 0) s_cnt = 0;
    for (int k = tid; k < NN; k += 256) s_lab[k] = labels[k];
    __syncthreads();

    const int lo = blockIdx.x * CELLS_PER_CTA;
    const int hi = min(lo + CELLS_PER_CTA, NN * NN);

    // phase 1: thread-granular label gate
    for (int p = lo + tid; p < hi; p += 256) {
        const int i = p / NN;
        const int j = p - i * NN;
        if (j > i && s_lab[i] == s_lab[j]) {
            int pos = atomicAdd(&s_cnt, 1);
            s_pairs[pos] = ((unsigned)i << 16) | (unsigned)j;
        }
    }
    __syncthreads();
    const int cnt = s_cnt;

    // phase 2: warp per pair
    for (int q = warp; q < cnt; q += 8) {
        const unsigned ij = s_pairs[q];
        const int i = (int)(ij >> 16);
        const int j = (int)(ij & 0xffffu);

        const uint4* __restrict__ bi = reinterpret_cast<const uint4*>(g_bits + i * WSTRIDE);
        const uint4* __restrict__ bj = reinterpret_cast<const uint4*>(g_bits + j * WSTRIDE);

        int inter = 0;
#pragma unroll 5
        for (int w = lane; w < WSTRIDE / 4; w += 32) {   // 15 iterations
            uint4 a = bi[w];
            uint4 b = bj[w];
            inter += __popc(a.x & b.x) + __popc(a.y & b.y)
                   + __popc(a.z & b.z) + __popc(a.w & b.w);
        }
#pragma unroll
        for (int off = 16; off > 0; off >>= 1)
            inter += __shfl_down_sync(0xffffffffu, inter, off);

        if (lane == 0) {
            float uni = g_areaf[i] + g_areaf[j] - (float)inter;
            float iou = (float)inter / fmaxf(uni, 1e-6f);
            atomicMax(reinterpret_cast<int*>(&g_comp[j]), __float_as_int(iou)); // iou>=0
            int pos = atomicAdd(&g_npairs, 1);
            g_pair_ij[pos] = ij;
            g_pair_d[pos] = iou;
        }
    }
}

// ============================================================
// Kernel 3 (single block, tiny data): scores + decay + output + reset.
// ============================================================
__global__ __launch_bounds__(1024) void decayfinal_kernel(
    const float* __restrict__ cate_scores,
    float* __restrict__ out)
{
    __shared__ float s_coef[NN];
    __shared__ float s_score[NN];
    const int tid = threadIdx.x;

    // phase 1: fixed-order reduce of 8 chunk partials per mask
    for (int n = tid; n < NN; n += 1024) {
        float acc = 0.0f;
#pragma unroll
        for (int k = 0; k < NCHUNK; k++) acc += g_part8[n * NCHUNK + k];
        s_score[n] = cate_scores[n] * (acc / fmaxf(g_areaf[n], 1.0f));
        s_coef[n] = 1.0f;
    }
    __syncthreads();

    // phase 2: decay terms -> order-independent min into smem coef
    const int np = g_npairs;
    for (int p = tid; p < np; p += 1024) {
        const unsigned ij = g_pair_ij[p];
        const int i = (int)(ij >> 16);
        const int j = (int)(ij & 0xffffu);
        const float d = g_pair_d[p];
        const float c = g_comp[i];
        const float term = __expf(SIGMA * (c * c - d * d));   // > 0
        atomicMin(reinterpret_cast<int*>(&s_coef[j]), __float_as_int(term));
    }
    __syncthreads();

    // phase 3: output + reset accumulators for next replay
    for (int n = tid; n < NN; n += 1024) {
        out[n] = s_score[n] * fminf(s_coef[n], 1.0f);
        g_areaf[n] = 0.0f;
        g_comp[n] = 0.0f;
    }
    if (tid == 0) g_npairs = 0;
}

extern "C" void kernel_launch(void* const* d_in, const int* in_sizes, int n_in,
                              void* d_out, int out_size)
{
    const float* cate_scores = (const float*)d_in[0];
    const float* segx        = (const float*)d_in[1];
    const float* segy        = (const float*)d_in[2];
    const int*   labels      = (const int*)d_in[3];
    const int*   x_inds      = (const int*)d_in[4];
    const int*   y_inds      = (const int*)d_in[5];
    float* out = (float*)d_out;

    decode_kernel<<<NN * NCHUNK, 256>>>(segx, segy, x_inds, y_inds);
    popc_kernel<<<POPC_BLOCKS, 256>>>(labels);
    decayfinal_kernel<<<1, 1024>>>(cate_scores, out);
}